// round 3
// baseline (speedup 1.0000x reference)
#include <cuda_runtime.h>
#include <cuda_bf16.h>

// Batched Thomas tridiagonal solve, B=2048 rows, N=8192 cols.
//   a_i = alpha[i-1]^2 (a_0=0), b_i = 1 + alpha[i]^3,
//   c_i = alpha[i+1]^2 + 2*alpha[i+1] (c_{N-1}=0), rhs f broadcast over rows.
// Forward:  den = b - a*cp_prev; cp = c/den; dp = (f - a*dp_prev)/den
// Backward: u_i = dp_i - cp_i * u_{i+1}
//
// Diagonal dominance (alpha in [0,0.3)) => forward state contracts <=0.097/step,
// backward contracts <=0.7394/step. Each thread solves one 128-col chunk of one
// row with a 16-col forward halo and 32-col backward halo (boundary error
// <= 0.7394^32 ~ 6e-5 worst case, ~1e-16 typical). Fully parallel.

#define N_COLS  8192
#define L_OWN   128
#define HF      16
#define HB      32
#define SPAN_C  177          // HF + L_OWN + HB + 1 (odd pitch -> conflict-free LDS)
#define NT_MAX  10
#define TPB     128
#define SMEM_BYTES ((TPB * SPAN_C + SPAN_C) * 4)

__global__ __launch_bounds__(TPB)
void thomas_chunk_kernel(const float* __restrict__ alpha,
                         const float* __restrict__ f,
                         float* __restrict__ out)
{
    extern __shared__ float smem[];              // [TPB][SPAN_C] alpha, then [SPAN_C] f
    float* fS = smem + TPB * SPAN_C;

    const int tid  = threadIdx.x;
    const int cc   = blockIdx.x;                 // chunk column (0..63)
    const int row0 = blockIdx.y * TPB;
    const int s    = cc * L_OWN;                 // first owned column
    const int col0 = s - HF;                     // first staged column (can be -16)

    // ---- stage alpha tile (coalesced LDG, conflict-free STS) ----
    for (int i = tid; i < TPB * SPAN_C; i += TPB) {
        int r = i / SPAN_C;
        int c = i - r * SPAN_C;
        int col = col0 + c;
        float v = 0.0f;
        if (col >= 0 && col < N_COLS)
            v = alpha[(size_t)(row0 + r) * N_COLS + col];
        smem[i] = v;
    }
    for (int i = tid; i < SPAN_C; i += TPB) {
        int col = col0 + i;
        fS[i] = (col >= 0 && col < N_COLS) ? f[col] : 0.0f;
    }
    __syncthreads();

    const float* sA = smem + tid * SPAN_C;       // this thread's row of alpha

    const int rcEnd   = min(HF + L_OWN + HB, N_COLS - col0);  // 176, or 144 for cc=63
    const int tiles_n = (rcEnd - HF) >> 4;                    // 10, or 8 for cc=63
    const int rcStart = (cc == 0) ? HF : 0;

    float cp = 0.0f, dp = 0.0f;
    float sqim1 = 0.0f;                          // a_i = alpha[i-1]^2 (0 at row start / halo cut)
    float al  = sA[rcStart];
    float sqi = al * al;

    float ckcp[NT_MAX], ckdp[NT_MAX];

    // ---- phase 1a: forward warmup across the left halo ----
    for (int rc = rcStart; rc < HF; ++rc) {
        float alp1 = sA[rc + 1];
        float sq1  = alp1 * alp1;
        float bi   = fmaf(al, sqi, 1.0f);                 // 1 + alpha^3
        float ci   = fmaf(2.0f, alp1, sq1);               // alpha^2 + 2*alpha
        float den  = fmaf(-sqim1, cp, bi);
        float r;  asm("rcp.approx.f32 %0, %1;" : "=f"(r) : "f"(den));
        cp = ci * r;
        dp = fmaf(-sqim1, dp, fS[rc]) * r;
        sqim1 = sqi; sqi = sq1; al = alp1;
    }

    // ---- phase 1b: forward sweep, checkpoint state entering each 16-tile ----
    for (int k = 0; k < tiles_n; ++k) {
        ckcp[k] = cp; ckdp[k] = dp;
        const int base = HF + (k << 4);
        #pragma unroll
        for (int j = 0; j < 16; ++j) {
            int rc = base + j;
            float alp1 = sA[rc + 1];
            float sq1  = alp1 * alp1;
            float bi   = fmaf(al, sqi, 1.0f);
            float ci   = fmaf(2.0f, alp1, sq1);
            float den  = fmaf(-sqim1, cp, bi);
            float r;  asm("rcp.approx.f32 %0, %1;" : "=f"(r) : "f"(den));
            cp = ci * r;
            dp = fmaf(-sqim1, dp, fS[rc]) * r;
            sqim1 = sqi; sqi = sq1; al = alp1;
        }
    }

    // ---- phase 2: tiles descending; recompute cp/dp from checkpoint, then
    //      backward-substitute. u enters topmost tile as 0 (halo cut; exact at
    //      i = N-1 because zero-padded alpha makes c_{N-1} = 0). ----
    float u = 0.0f;
    for (int k = tiles_n - 1; k >= 0; --k) {
        const int base = HF + (k << 4);
        float cp2 = ckcp[k], dp2 = ckdp[k];
        float alm = sA[base - 1];
        float s1  = alm * alm;                   // rolling sqim1 (matches phase 1)
        float a2  = sA[base];
        float s2  = a2 * a2;
        float cpl[16], dpl[16];
        #pragma unroll
        for (int j = 0; j < 16; ++j) {
            float alp1 = sA[base + j + 1];
            float sq1  = alp1 * alp1;
            float bi   = fmaf(a2, s2, 1.0f);
            float ci   = fmaf(2.0f, alp1, sq1);
            float den  = fmaf(-s1, cp2, bi);
            float r;  asm("rcp.approx.f32 %0, %1;" : "=f"(r) : "f"(den));
            cp2 = ci * r;
            dp2 = fmaf(-s1, dp2, fS[base + j]) * r;
            cpl[j] = cp2; dpl[j] = dp2;
            s1 = s2; s2 = sq1; a2 = alp1;
        }
        #pragma unroll
        for (int j = 15; j >= 0; --j) {
            u = fmaf(-cpl[j], u, dpl[j]);
            dpl[j] = u;
        }
        if (k < 8) {                             // owned tiles only (k=8,9 = halo)
            float4* o4 = reinterpret_cast<float4*>(
                out + (size_t)(row0 + tid) * N_COLS + s + (k << 4));
            o4[0] = make_float4(dpl[0],  dpl[1],  dpl[2],  dpl[3]);
            o4[1] = make_float4(dpl[4],  dpl[5],  dpl[6],  dpl[7]);
            o4[2] = make_float4(dpl[8],  dpl[9],  dpl[10], dpl[11]);
            o4[3] = make_float4(dpl[12], dpl[13], dpl[14], dpl[15]);
        }
    }
}

extern "C" void kernel_launch(void* const* d_in, const int* in_sizes, int n_in,
                              void* d_out, int out_size)
{
    const float* alpha = (const float*)d_in[0];   // (2048, 8192) f32
    const float* f     = (const float*)d_in[1];   // (8192,) f32
    float* out         = (float*)d_out;           // (2048, 8192) f32

    static int smem_set = 0;  // idempotent attribute set (host-side, not a stream op)
    if (!smem_set) {
        cudaFuncSetAttribute(thomas_chunk_kernel,
                             cudaFuncAttributeMaxDynamicSharedMemorySize,
                             SMEM_BYTES);
        smem_set = 1;
    }

    dim3 grid(N_COLS / L_OWN, 2048 / TPB);        // (64, 16)
    thomas_chunk_kernel<<<grid, TPB, SMEM_BYTES>>>(alpha, f, out);
}